// round 15
// baseline (speedup 1.0000x reference)
#include <cuda_runtime.h>
#include <cuda_bf16.h>
#include <cuda_fp16.h>
#include <cstdint>

// ---------------- dims ----------------
#define B_    16
#define C_    256
#define O_    256
#define HW_   56
#define NPIX  3136
#define NK    8
#define HID   64
#define NKEL  589824          // 256*256*9 per bank
#define NT    784             // 28*28 winograd tiles
#define NTP   896             // padded tiles (7*128)
#define NXI   16

#define NCHUNK2 4
#define NSTG   3

// GEMM smem (fp16 units)
#define SW_ROW   72
#define SX_ROW   136
#define SW_STG   (128 * SW_ROW)               // 9216
#define SX_STG   (64 * SX_ROW)                // 8704
#define STG_ELEMS (SW_STG + SX_STG)           // 17920
#define SMEM_BYTES (NSTG * STG_ELEMS * 2)     // 107520
// mixU smem: sv 8*2304 + sal 128 + sp 4096 + sh 1024 + sc 128 floats
#define MIXU_FLOATS (8 * 2304 + 128 + B_ * C_ + B_ * HID + B_ * NK)
#define MIX_SMEM (MIXU_FLOATS * 4 + 256)

__device__ float g_pooled[B_ * C_];
// V: [b*16+xi][ic][NTP] fp16
__device__ __align__(16) unsigned short g_V[(size_t)B_ * NXI * C_ * NTP];
// U: [b*16+xi][o][ic] fp16
__device__ __align__(16) unsigned short g_U[(size_t)B_ * NXI * O_ * C_];
// M: [b*16+xi][o][NTP] fp16
__device__ __align__(16) unsigned short g_M[(size_t)B_ * NXI * O_ * NTP];

// ---------------- asm helpers ----------------
__device__ __forceinline__ uint32_t smem_u32(const void* p) {
    uint32_t a;
    asm("{ .reg .u64 t; cvta.to.shared.u64 t, %1; cvt.u32.u64 %0, t; }" : "=r"(a) : "l"(p));
    return a;
}
#define CP16(dst, src) asm volatile("cp.async.cg.shared.global [%0], [%1], 16;" :: "r"(dst), "l"(src))
#define CP_COMMIT()    asm volatile("cp.async.commit_group;" ::: "memory")
#define CP_WAIT(n)     asm volatile("cp.async.wait_group %0;" :: "n"(n) : "memory")

__device__ __forceinline__ void ldsm4(uint32_t* r, uint32_t a) {
    asm volatile("ldmatrix.sync.aligned.m8n8.x4.shared.b16 {%0,%1,%2,%3}, [%4];"
                 : "=r"(r[0]), "=r"(r[1]), "=r"(r[2]), "=r"(r[3]) : "r"(a));
}
__device__ __forceinline__ void ldsm4t(uint32_t* r, uint32_t a) {
    asm volatile("ldmatrix.sync.aligned.m8n8.x4.trans.shared.b16 {%0,%1,%2,%3}, [%4];"
                 : "=r"(r[0]), "=r"(r[1]), "=r"(r[2]), "=r"(r[3]) : "r"(a));
}
__device__ __forceinline__ void mma_f16(float* d, const uint32_t* a, const uint32_t* b) {
    asm volatile("mma.sync.aligned.m16n8k16.row.col.f32.f16.f16.f32 "
                 "{%0,%1,%2,%3}, {%4,%5,%6,%7}, {%8,%9}, {%0,%1,%2,%3};"
                 : "+f"(d[0]), "+f"(d[1]), "+f"(d[2]), "+f"(d[3])
                 : "r"(a[0]), "r"(a[1]), "r"(a[2]), "r"(a[3]), "r"(b[0]), "r"(b[1]));
}
__device__ __forceinline__ uint32_t h2u(float a, float b) {
    __half2 h = __floats2half2_rn(a, b);
    return *(uint32_t*)&h;
}

// ---------------- Kernel 1: input transform V = B^T d B (+pool fused) ----------
__global__ void __launch_bounds__(256)
inputT_kernel(const float* __restrict__ x) {
    const int ic = blockIdx.x, b = blockIdx.y;
    __shared__ float sp[NPIX];
    __shared__ float red[8];
    const float4* xp = (const float4*)(x + ((size_t)(b * C_ + ic)) * NPIX);
    float s = 0.f;
    for (int i = threadIdx.x; i < NPIX / 4; i += 256) {
        float4 v = xp[i];
        *(float4*)&sp[i * 4] = v;
        s += (v.x + v.y) + (v.z + v.w);
    }
    #pragma unroll
    for (int o = 16; o > 0; o >>= 1) s += __shfl_xor_sync(0xffffffffu, s, o);
    if ((threadIdx.x & 31) == 0) red[threadIdx.x >> 5] = s;
    __syncthreads();
    if (threadIdx.x < 8) {
        s = red[threadIdx.x];
        #pragma unroll
        for (int o = 4; o > 0; o >>= 1) s += __shfl_xor_sync(0xffu, s, o);
        if (threadIdx.x == 0) g_pooled[b * C_ + ic] = s * (1.0f / NPIX);
    }

    const size_t vbase = ((size_t)(b * NXI)) * C_ * NTP + (size_t)ic * NTP;

    for (int p = threadIdx.x; p < NT / 2; p += 256) {
        int t0 = p * 2;
        int ty = t0 / 28, tx0 = t0 % 28;
        int r0 = 2 * ty - 1, c0 = 2 * tx0 - 1;
        float d[4][6];
        #pragma unroll
        for (int i = 0; i < 4; i++) {
            int r = r0 + i;
            bool rv = (r >= 0 && r < HW_);
            #pragma unroll
            for (int j = 0; j < 6; j++) {
                int c = c0 + j;
                d[i][j] = (rv && c >= 0 && c < HW_) ? sp[r * HW_ + c] : 0.f;
            }
        }
        float V0[16], V1[16];
        #pragma unroll
        for (int tt = 0; tt < 2; tt++) {
            int jo = 2 * tt;
            float tr[4][4];
            #pragma unroll
            for (int c = 0; c < 4; c++) {
                tr[0][c] = d[0][jo + c] - d[2][jo + c];
                tr[1][c] = d[1][jo + c] + d[2][jo + c];
                tr[2][c] = d[2][jo + c] - d[1][jo + c];
                tr[3][c] = d[1][jo + c] - d[3][jo + c];
            }
            float* V = tt ? V1 : V0;
            #pragma unroll
            for (int r = 0; r < 4; r++) {
                V[r * 4 + 0] = tr[r][0] - tr[r][2];
                V[r * 4 + 1] = tr[r][1] + tr[r][2];
                V[r * 4 + 2] = tr[r][2] - tr[r][1];
                V[r * 4 + 3] = tr[r][1] - tr[r][3];
            }
        }
        #pragma unroll
        for (int xi = 0; xi < 16; xi++) {
            size_t idx = vbase + (size_t)xi * (C_ * NTP) + t0;
            *(uint32_t*)&g_V[idx] = h2u(V0[xi], V1[xi]);
        }
    }
    for (int p = threadIdx.x; p < (NTP - NT) / 2; p += 256) {
        int t0 = NT + p * 2;
        #pragma unroll
        for (int xi = 0; xi < 16; xi++) {
            size_t idx = vbase + (size_t)xi * (C_ * NTP) + t0;
            *(uint32_t*)&g_V[idx] = 0u;
        }
    }
}

// ---------------- Kernel 2: MLP (redundant per block) + mix + transform U ------
extern __shared__ float mixsm[];
__global__ void __launch_bounds__(256)
mixU_kernel(const float* __restrict__ kern,
            const float* __restrict__ w1, const float* __restrict__ b1,
            const float* __restrict__ w2, const float* __restrict__ b2) {
    float* sv  = mixsm;                    // [8][2304]
    float* sal = sv + 8 * 2304;            // [128]
    float* sp  = sal + 128;                // [B_*C_]
    float* sh  = sp + B_ * C_;             // [B_*HID]
    float* sc  = sh + B_ * HID;            // [B_*NK]
    const int o = blockIdx.x, tid = threadIdx.x;

    // kernel-bank loads (independent of MLP)
    #pragma unroll
    for (int k = 0; k < 8; k++)
        for (int i = tid; i < 2304; i += 256)
            sv[k * 2304 + i] = kern[(size_t)k * NKEL + (size_t)o * 2304 + i];

    // MLP + softmax (deterministic, redundant per block)
    for (int i = tid; i < B_ * C_; i += 256) sp[i] = g_pooled[i];
    __syncthreads();
    for (int t = tid; t < B_ * HID; t += 256) {
        int b = t >> 6, j = t & 63;
        float s = b1[j];
        #pragma unroll 8
        for (int c = 0; c < C_; c++) s = fmaf(sp[b * C_ + c], w1[c * HID + j], s);
        sh[t] = fmaxf(s, 0.f);
    }
    __syncthreads();
    if (tid < B_ * NK) {
        int b = tid >> 3, k = tid & 7;
        float s = b2[k];
        #pragma unroll
        for (int j = 0; j < HID; j++) s = fmaf(sh[b * HID + j], w2[j * NK + k], s);
        sc[tid] = s;
    }
    __syncthreads();
    if (tid < B_) {
        float m = -1e30f;
        #pragma unroll
        for (int k = 0; k < NK; k++) m = fmaxf(m, sc[tid * NK + k]);
        float e[NK], sum = 0.f;
        #pragma unroll
        for (int k = 0; k < NK; k++) { e[k] = __expf(sc[tid * NK + k] - m); sum += e[k]; }
        float inv = 1.0f / sum;
        #pragma unroll
        for (int k = 0; k < NK; k++) sal[tid * NK + k] = e[k] * inv;
    }
    __syncthreads();

    const int ic = tid;
    #pragma unroll
    for (int b = 0; b < B_; b++) {
        float g[3][3];
        #pragma unroll
        for (int r = 0; r < 3; r++)
            #pragma unroll
            for (int c = 0; c < 3; c++) {
                float sum = 0.f;
                #pragma unroll
                for (int k = 0; k < 8; k++)
                    sum = fmaf(sal[b * NK + k], sv[k * 2304 + ic * 9 + r * 3 + c], sum);
                g[r][c] = sum;
            }
        float q[4][3];
        #pragma unroll
        for (int c = 0; c < 3; c++) {
            q[0][c] = g[0][c];
            q[1][c] = 0.5f * (g[0][c] + g[1][c] + g[2][c]);
            q[2][c] = 0.5f * (g[0][c] - g[1][c] + g[2][c]);
            q[3][c] = g[2][c];
        }
        #pragma unroll
        for (int r = 0; r < 4; r++) {
            float U0 = q[r][0];
            float U1 = 0.5f * (q[r][0] + q[r][1] + q[r][2]);
            float U2 = 0.5f * (q[r][0] - q[r][1] + q[r][2]);
            float U3 = q[r][2];
            int xibase = r * 4;
            size_t base = ((size_t)(b * NXI) * O_ + o) * C_ + ic;
            g_U[base + (size_t)(xibase + 0) * (O_ * C_)] = __half_as_ushort(__float2half_rn(U0));
            g_U[base + (size_t)(xibase + 1) * (O_ * C_)] = __half_as_ushort(__float2half_rn(U1));
            g_U[base + (size_t)(xibase + 2) * (O_ * C_)] = __half_as_ushort(__float2half_rn(U2));
            g_U[base + (size_t)(xibase + 3) * (O_ * C_)] = __half_as_ushort(__float2half_rn(U3));
        }
    }
}

// ---------------- Kernel 3: batched GEMM M[bxi] = U[bxi] * V[bxi] ----------------
extern __shared__ __align__(16) unsigned short dynsm[];

__global__ void __launch_bounds__(256, 2)
wino_gemm(int dummy) {
    const int tid = threadIdx.x;
    const int n0 = blockIdx.x * 128;
    const int o0 = blockIdx.y * 128;
    const int bxi = blockIdx.z;

    const int warp = tid >> 5, L = tid & 31;
    const int wo = (warp >> 2) << 6;
    const int wp = (warp & 3) << 5;
    const int gid = L >> 2, tid4 = L & 3;

    const uint32_t sbase = smem_u32(dynsm);
    const int aRow = wo + (L & 15);
    const int aCol = (L >> 4) << 3;
    const int xRow = L & 15;
    const int xCol = wp + ((L >> 4) << 3);

    int wRow[4], wJ[4], xKK[4], xJ[4];
    #pragma unroll
    for (int i = 0; i < 4; i++) {
        int e = tid + i * 256;
        wRow[i] = e >> 3; wJ[i] = e & 7;
        xKK[i] = e >> 4; xJ[i] = e & 15;
    }

    float acc[4][4][4];
    #pragma unroll
    for (int mt = 0; mt < 4; mt++)
        #pragma unroll
        for (int nt = 0; nt < 4; nt++)
            #pragma unroll
            for (int r = 0; r < 4; r++) acc[mt][nt][r] = 0.f;

    const unsigned short* Ub = g_U + (size_t)bxi * (O_ * C_);
    const unsigned short* Vb = g_V + (size_t)bxi * (C_ * NTP);

    auto load_chunk = [&](int c, int stg) {
        uint32_t sb = sbase + (uint32_t)stg * (STG_ELEMS * 2);
        #pragma unroll
        for (int i = 0; i < 4; i++) {
            const unsigned short* srcw = Ub + (size_t)(o0 + wRow[i]) * C_ + c * 64 + wJ[i] * 8;
            CP16(sb + 2u * (wRow[i] * SW_ROW + wJ[i] * 8), srcw);
            const unsigned short* srcx = Vb + (size_t)(c * 64 + xKK[i]) * NTP + n0 + xJ[i] * 8;
            CP16(sb + 2u * (SW_STG + xKK[i] * SX_ROW + xJ[i] * 8), srcx);
        }
    };

    load_chunk(0, 0); CP_COMMIT();
    load_chunk(1, 1); CP_COMMIT();

    int stage = 0;
    for (int c = 0; c < NCHUNK2; c++) {
        if (c < NCHUNK2 - 1) { CP_WAIT(1); } else { CP_WAIT(0); }
        __syncthreads();
        if (c + 2 < NCHUNK2) {
            int s2 = stage + 2; if (s2 >= NSTG) s2 -= NSTG;
            load_chunk(c + 2, s2);
            CP_COMMIT();
        }

        const uint32_t sb = sbase + (uint32_t)stage * (STG_ELEMS * 2);
        #pragma unroll
        for (int ks = 0; ks < 4; ks++) {
            uint32_t A[4][4], Bh[2][4];
            #pragma unroll
            for (int mt = 0; mt < 4; mt++) {
                uint32_t a = sb + 2u * ((aRow + mt * 16) * SW_ROW + ks * 16 + aCol);
                ldsm4(A[mt], a);
            }
            #pragma unroll
            for (int np = 0; np < 2; np++) {
                uint32_t a = sb + 2u * (SW_STG + (ks * 16 + xRow) * SX_ROW + xCol + np * 16);
                ldsm4t(Bh[np], a);
            }
            #pragma unroll
            for (int mt = 0; mt < 4; mt++)
                #pragma unroll
                for (int nt = 0; nt < 4; nt++)
                    mma_f16(acc[mt][nt], A[mt], &Bh[nt >> 1][(nt & 1) * 2]);
        }
        stage = stage + 1; if (stage >= NSTG) stage -= NSTG;
    }

    unsigned short* Mb = g_M + (size_t)bxi * (O_ * NTP);
    #pragma unroll
    for (int mt = 0; mt < 4; mt++) {
        #pragma unroll
        for (int nt = 0; nt < 4; nt++) {
            int o = o0 + wo + mt * 16 + gid;
            int pix = n0 + wp + nt * 8 + tid4 * 2;
            *(uint32_t*)&Mb[(size_t)o * NTP + pix]       = h2u(acc[mt][nt][0], acc[mt][nt][1]);
            *(uint32_t*)&Mb[(size_t)(o + 8) * NTP + pix] = h2u(acc[mt][nt][2], acc[mt][nt][3]);
        }
    }
}

// ---------------- Kernel 4: inverse transform, 4-tile vector groups ----------
__global__ void __launch_bounds__(256)
inverseT_kernel(float* __restrict__ out) {
    const int o = blockIdx.x, b = blockIdx.y;
    const size_t mbase = ((size_t)(b * NXI)) * O_ * NTP + (size_t)o * NTP;
    const size_t obase = ((size_t)(b * O_ + o)) * NPIX;

    // 196 groups of 4 consecutive tiles (28 % 4 == 0: never cross tile rows)
    for (int g = threadIdx.x; g < NT / 4; g += 256) {
        int t0 = g * 4;
        int ty = t0 / 28, tx0 = t0 % 28;
        float m[16][4];
        #pragma unroll
        for (int xi = 0; xi < 16; xi++) {
            uint2 v = *(const uint2*)&g_M[mbase + (size_t)xi * (O_ * NTP) + t0];
            __half2 h0 = *(__half2*)&v.x;
            __half2 h1 = *(__half2*)&v.y;
            m[xi][0] = __low2float(h0);  m[xi][1] = __high2float(h0);
            m[xi][2] = __low2float(h1);  m[xi][3] = __high2float(h1);
        }
        float row0[8], row1[8];
        #pragma unroll
        for (int j = 0; j < 4; j++) {
            float sr0[4], sr1[4];
            #pragma unroll
            for (int c = 0; c < 4; c++) {
                sr0[c] = m[0 * 4 + c][j] + m[1 * 4 + c][j] + m[2 * 4 + c][j];
                sr1[c] = m[1 * 4 + c][j] - m[2 * 4 + c][j] - m[3 * 4 + c][j];
            }
            row0[j * 2 + 0] = sr0[0] + sr0[1] + sr0[2];
            row0[j * 2 + 1] = sr0[1] - sr0[2] - sr0[3];
            row1[j * 2 + 0] = sr1[0] + sr1[1] + sr1[2];
            row1[j * 2 + 1] = sr1[1] - sr1[2] - sr1[3];
        }
        size_t pb = obase + (size_t)(2 * ty) * HW_ + 2 * tx0;
        *(float4*)&out[pb]           = make_float4(row0[0], row0[1], row0[2], row0[3]);
        *(float4*)&out[pb + 4]       = make_float4(row0[4], row0[5], row0[6], row0[7]);
        *(float4*)&out[pb + HW_]     = make_float4(row1[0], row1[1], row1[2], row1[3]);
        *(float4*)&out[pb + HW_ + 4] = make_float4(row1[4], row1[5], row1[6], row1[7]);
    }
}

extern "C" void kernel_launch(void* const* d_in, const int* in_sizes, int n_in,
                              void* d_out, int out_size) {
    const float* x    = (const float*)d_in[0];
    const float* kern = (const float*)d_in[1];
    const float* w1   = (const float*)d_in[2];
    const float* b1   = (const float*)d_in[3];
    const float* w2   = (const float*)d_in[4];
    const float* b2   = (const float*)d_in[5];
    float* out = (float*)d_out;

    cudaFuncSetAttribute(wino_gemm, cudaFuncAttributeMaxDynamicSharedMemorySize, SMEM_BYTES);
    cudaFuncSetAttribute(mixU_kernel, cudaFuncAttributeMaxDynamicSharedMemorySize, MIX_SMEM);

    inputT_kernel<<<dim3(C_, B_), 256>>>(x);
    mixU_kernel<<<O_, 256, MIX_SMEM>>>(kern, w1, b1, w2, b2);
    wino_gemm<<<dim3(7, 2, B_ * NXI), 256, SMEM_BYTES>>>(0);
    inverseT_kernel<<<dim3(O_, B_), 256>>>(out);
}

// round 16
// speedup vs baseline: 1.0042x; 1.0042x over previous
#include <cuda_runtime.h>
#include <cuda_bf16.h>
#include <cuda_fp16.h>
#include <cstdint>

// ---------------- dims ----------------
#define B_    16
#define C_    256
#define O_    256
#define HW_   56
#define NPIX  3136
#define NK    8
#define HID   64
#define NKEL  589824          // 256*256*9 per bank
#define NT    784             // 28*28 winograd tiles
#define NTP   896             // padded tiles (7*128)
#define NXI   16

#define NCHUNK2 4
#define NSTG   3

// GEMM smem (fp16 units)
#define SW_ROW   72
#define SX_ROW   136
#define SW_STG   (128 * SW_ROW)               // 9216
#define SX_STG   (64 * SX_ROW)                // 8704
#define STG_ELEMS (SW_STG + SX_STG)           // 17920
#define SMEM_BYTES (NSTG * STG_ELEMS * 2)     // 107520
#define MIX_SMEM  (8 * 2304 * 4 + 512)        // 74240

__device__ float g_ppart[2][B_ * C_];
__device__ float g_alphas[B_ * NK];
// V: [b*16+xi][ic][NTP] fp16
__device__ __align__(16) unsigned short g_V[(size_t)B_ * NXI * C_ * NTP];
// U: [b*16+xi][o][ic] fp16
__device__ __align__(16) unsigned short g_U[(size_t)B_ * NXI * O_ * C_];
// M: [b*16+xi][o][NTP] fp16
__device__ __align__(16) unsigned short g_M[(size_t)B_ * NXI * O_ * NTP];

// ---------------- asm helpers ----------------
__device__ __forceinline__ uint32_t smem_u32(const void* p) {
    uint32_t a;
    asm("{ .reg .u64 t; cvta.to.shared.u64 t, %1; cvt.u32.u64 %0, t; }" : "=r"(a) : "l"(p));
    return a;
}
#define CP16(dst, src) asm volatile("cp.async.cg.shared.global [%0], [%1], 16;" :: "r"(dst), "l"(src))
#define CP_COMMIT()    asm volatile("cp.async.commit_group;" ::: "memory")
#define CP_WAIT(n)     asm volatile("cp.async.wait_group %0;" :: "n"(n) : "memory")

__device__ __forceinline__ void ldsm4(uint32_t* r, uint32_t a) {
    asm volatile("ldmatrix.sync.aligned.m8n8.x4.shared.b16 {%0,%1,%2,%3}, [%4];"
                 : "=r"(r[0]), "=r"(r[1]), "=r"(r[2]), "=r"(r[3]) : "r"(a));
}
__device__ __forceinline__ void ldsm4t(uint32_t* r, uint32_t a) {
    asm volatile("ldmatrix.sync.aligned.m8n8.x4.trans.shared.b16 {%0,%1,%2,%3}, [%4];"
                 : "=r"(r[0]), "=r"(r[1]), "=r"(r[2]), "=r"(r[3]) : "r"(a));
}
__device__ __forceinline__ void mma_f16(float* d, const uint32_t* a, const uint32_t* b) {
    asm volatile("mma.sync.aligned.m16n8k16.row.col.f32.f16.f16.f32 "
                 "{%0,%1,%2,%3}, {%4,%5,%6,%7}, {%8,%9}, {%0,%1,%2,%3};"
                 : "+f"(d[0]), "+f"(d[1]), "+f"(d[2]), "+f"(d[3])
                 : "r"(a[0]), "r"(a[1]), "r"(a[2]), "r"(a[3]), "r"(b[0]), "r"(b[1]));
}
__device__ __forceinline__ uint32_t h2u(float a, float b) {
    __half2 h = __floats2half2_rn(a, b);
    return *(uint32_t*)&h;
}

// ---------------- Kernel 1: input transform (half-image blocks) + partial pool --
// Block: (ic, b, half). half 0 = tile rows 0..13, half 1 = tile rows 14..27.
// Loads 29 x-rows (with halo), transforms 196 tile-pairs, partial pool sum.
__global__ void __launch_bounds__(256)
inputT_kernel(const float* __restrict__ x) {
    const int ic = blockIdx.x, b = blockIdx.y, half = blockIdx.z;
    __shared__ float sp[29 * HW_];
    __shared__ float red[8];

    const int lo = half ? 27 : 0;            // first loaded row
    const int plo = half * 28;                // pool rows [plo, plo+27]
    const float4* xp = (const float4*)(x + ((size_t)(b * C_ + ic)) * NPIX);

    float s = 0.f;
    // 29 rows x 14 float4 = 406 vector loads
    for (int i = threadIdx.x; i < 29 * 14; i += 256) {
        int rl = i / 14, c4 = i % 14;
        int r = lo + rl;
        float4 v = xp[r * 14 + c4];
        *(float4*)&sp[rl * HW_ + c4 * 4] = v;
        if (r >= plo && r < plo + 28)
            s += (v.x + v.y) + (v.z + v.w);
    }
    #pragma unroll
    for (int o = 16; o > 0; o >>= 1) s += __shfl_xor_sync(0xffffffffu, s, o);
    if ((threadIdx.x & 31) == 0) red[threadIdx.x >> 5] = s;
    __syncthreads();
    if (threadIdx.x < 8) {
        s = red[threadIdx.x];
        #pragma unroll
        for (int o = 4; o > 0; o >>= 1) s += __shfl_xor_sync(0xffu, s, o);
        if (threadIdx.x == 0) g_ppart[half][b * C_ + ic] = s;
    }

    const size_t vbase = ((size_t)(b * NXI)) * C_ * NTP + (size_t)ic * NTP;
    const int tbase = half * 392;             // global tile offset for this half

    // 196 tile-pairs in this half
    for (int p = threadIdx.x; p < 196; p += 256) {
        int t0l = p * 2;
        int tyl = t0l / 28, tx0 = t0l % 28;
        int ty = half * 14 + tyl;
        int r0 = 2 * ty - 1, c0 = 2 * tx0 - 1;
        float d[4][6];
        #pragma unroll
        for (int i = 0; i < 4; i++) {
            int r = r0 + i;
            bool rv = (r >= 0 && r < HW_);
            int rl = r - lo;
            #pragma unroll
            for (int j = 0; j < 6; j++) {
                int c = c0 + j;
                d[i][j] = (rv && c >= 0 && c < HW_) ? sp[rl * HW_ + c] : 0.f;
            }
        }
        float V0[16], V1[16];
        #pragma unroll
        for (int tt = 0; tt < 2; tt++) {
            int jo = 2 * tt;
            float tr[4][4];
            #pragma unroll
            for (int c = 0; c < 4; c++) {
                tr[0][c] = d[0][jo + c] - d[2][jo + c];
                tr[1][c] = d[1][jo + c] + d[2][jo + c];
                tr[2][c] = d[2][jo + c] - d[1][jo + c];
                tr[3][c] = d[1][jo + c] - d[3][jo + c];
            }
            float* V = tt ? V1 : V0;
            #pragma unroll
            for (int r = 0; r < 4; r++) {
                V[r * 4 + 0] = tr[r][0] - tr[r][2];
                V[r * 4 + 1] = tr[r][1] + tr[r][2];
                V[r * 4 + 2] = tr[r][2] - tr[r][1];
                V[r * 4 + 3] = tr[r][1] - tr[r][3];
            }
        }
        int tg = tbase + t0l;
        #pragma unroll
        for (int xi = 0; xi < 16; xi++) {
            size_t idx = vbase + (size_t)xi * (C_ * NTP) + tg;
            *(uint32_t*)&g_V[idx] = h2u(V0[xi], V1[xi]);
        }
    }
    // zero pad region t in [784, 896) — half 0 only
    if (half == 0) {
        for (int p = threadIdx.x; p < (NTP - NT) / 2; p += 256) {
            int t0 = NT + p * 2;
            #pragma unroll
            for (int xi = 0; xi < 16; xi++) {
                size_t idx = vbase + (size_t)xi * (C_ * NTP) + t0;
                *(uint32_t*)&g_V[idx] = 0u;
            }
        }
    }
}

// ---------------- Kernel 2: MLP + softmax ----------------
__global__ void mlp_kernel(const float* __restrict__ w1, const float* __restrict__ b1,
                           const float* __restrict__ w2, const float* __restrict__ b2) {
    __shared__ float sp[B_ * C_];
    __shared__ float sh[B_ * HID];
    __shared__ float sc[B_ * NK];
    int tid = threadIdx.x;
    for (int i = tid; i < B_ * C_; i += 256)
        sp[i] = (g_ppart[0][i] + g_ppart[1][i]) * (1.0f / NPIX);
    __syncthreads();
    for (int t = tid; t < B_ * HID; t += 256) {
        int b = t >> 6, j = t & 63;
        float s = b1[j];
        #pragma unroll 8
        for (int c = 0; c < C_; c++) s = fmaf(sp[b * C_ + c], w1[c * HID + j], s);
        sh[t] = fmaxf(s, 0.f);
    }
    __syncthreads();
    if (tid < B_ * NK) {
        int b = tid >> 3, k = tid & 7;
        float s = b2[k];
        #pragma unroll
        for (int j = 0; j < HID; j++) s = fmaf(sh[b * HID + j], w2[j * NK + k], s);
        sc[tid] = s;
    }
    __syncthreads();
    if (tid < B_) {
        float m = -1e30f;
        #pragma unroll
        for (int k = 0; k < NK; k++) m = fmaxf(m, sc[tid * NK + k]);
        float e[NK], sum = 0.f;
        #pragma unroll
        for (int k = 0; k < NK; k++) { e[k] = __expf(sc[tid * NK + k] - m); sum += e[k]; }
        float inv = 1.0f / sum;
        #pragma unroll
        for (int k = 0; k < NK; k++) g_alphas[tid * NK + k] = e[k] * inv;
    }
}

// ---------------- Kernel 3: weight mix + transform U = G g G^T ----------------
extern __shared__ float mixsm[];
__global__ void mixU_kernel(const float* __restrict__ kern) {
    float* sv = mixsm;
    float* sal = mixsm + 8 * 2304;
    const int o = blockIdx.x, tid = threadIdx.x;
    if (tid < B_ * NK) sal[tid] = g_alphas[tid];
    #pragma unroll
    for (int k = 0; k < 8; k++)
        for (int i = tid; i < 2304; i += 256)
            sv[k * 2304 + i] = kern[(size_t)k * NKEL + (size_t)o * 2304 + i];
    __syncthreads();

    const int ic = tid;
    #pragma unroll
    for (int b = 0; b < B_; b++) {
        float g[3][3];
        #pragma unroll
        for (int r = 0; r < 3; r++)
            #pragma unroll
            for (int c = 0; c < 3; c++) {
                float sum = 0.f;
                #pragma unroll
                for (int k = 0; k < 8; k++)
                    sum = fmaf(sal[b * NK + k], sv[k * 2304 + ic * 9 + r * 3 + c], sum);
                g[r][c] = sum;
            }
        float q[4][3];
        #pragma unroll
        for (int c = 0; c < 3; c++) {
            q[0][c] = g[0][c];
            q[1][c] = 0.5f * (g[0][c] + g[1][c] + g[2][c]);
            q[2][c] = 0.5f * (g[0][c] - g[1][c] + g[2][c]);
            q[3][c] = g[2][c];
        }
        #pragma unroll
        for (int r = 0; r < 4; r++) {
            float U0 = q[r][0];
            float U1 = 0.5f * (q[r][0] + q[r][1] + q[r][2]);
            float U2 = 0.5f * (q[r][0] - q[r][1] + q[r][2]);
            float U3 = q[r][2];
            int xibase = r * 4;
            size_t base = ((size_t)(b * NXI) * O_ + o) * C_ + ic;
            g_U[base + (size_t)(xibase + 0) * (O_ * C_)] = __half_as_ushort(__float2half_rn(U0));
            g_U[base + (size_t)(xibase + 1) * (O_ * C_)] = __half_as_ushort(__float2half_rn(U1));
            g_U[base + (size_t)(xibase + 2) * (O_ * C_)] = __half_as_ushort(__float2half_rn(U2));
            g_U[base + (size_t)(xibase + 3) * (O_ * C_)] = __half_as_ushort(__float2half_rn(U3));
        }
    }
}

// ---------------- Kernel 4: batched GEMM M[bxi] = U[bxi] * V[bxi] ----------------
extern __shared__ __align__(16) unsigned short dynsm[];

__global__ void __launch_bounds__(256, 2)
wino_gemm(int dummy) {
    const int tid = threadIdx.x;
    const int n0 = blockIdx.x * 128;
    const int o0 = blockIdx.y * 128;
    const int bxi = blockIdx.z;

    const int warp = tid >> 5, L = tid & 31;
    const int wo = (warp >> 2) << 6;
    const int wp = (warp & 3) << 5;
    const int gid = L >> 2, tid4 = L & 3;

    const uint32_t sbase = smem_u32(dynsm);
    const int aRow = wo + (L & 15);
    const int aCol = (L >> 4) << 3;
    const int xRow = L & 15;
    const int xCol = wp + ((L >> 4) << 3);

    int wRow[4], wJ[4], xKK[4], xJ[4];
    #pragma unroll
    for (int i = 0; i < 4; i++) {
        int e = tid + i * 256;
        wRow[i] = e >> 3; wJ[i] = e & 7;
        xKK[i] = e >> 4; xJ[i] = e & 15;
    }

    float acc[4][4][4];
    #pragma unroll
    for (int mt = 0; mt < 4; mt++)
        #pragma unroll
        for (int nt = 0; nt < 4; nt++)
            #pragma unroll
            for (int r = 0; r < 4; r++) acc[mt][nt][r] = 0.f;

    const unsigned short* Ub = g_U + (size_t)bxi * (O_ * C_);
    const unsigned short* Vb = g_V + (size_t)bxi * (C_ * NTP);

    auto load_chunk = [&](int c, int stg) {
        uint32_t sb = sbase + (uint32_t)stg * (STG_ELEMS * 2);
        #pragma unroll
        for (int i = 0; i < 4; i++) {
            const unsigned short* srcw = Ub + (size_t)(o0 + wRow[i]) * C_ + c * 64 + wJ[i] * 8;
            CP16(sb + 2u * (wRow[i] * SW_ROW + wJ[i] * 8), srcw);
            const unsigned short* srcx = Vb + (size_t)(c * 64 + xKK[i]) * NTP + n0 + xJ[i] * 8;
            CP16(sb + 2u * (SW_STG + xKK[i] * SX_ROW + xJ[i] * 8), srcx);
        }
    };

    load_chunk(0, 0); CP_COMMIT();
    load_chunk(1, 1); CP_COMMIT();

    int stage = 0;
    for (int c = 0; c < NCHUNK2; c++) {
        if (c < NCHUNK2 - 1) { CP_WAIT(1); } else { CP_WAIT(0); }
        __syncthreads();
        if (c + 2 < NCHUNK2) {
            int s2 = stage + 2; if (s2 >= NSTG) s2 -= NSTG;
            load_chunk(c + 2, s2);
            CP_COMMIT();
        }

        const uint32_t sb = sbase + (uint32_t)stage * (STG_ELEMS * 2);
        #pragma unroll
        for (int ks = 0; ks < 4; ks++) {
            uint32_t A[4][4], Bh[2][4];
            #pragma unroll
            for (int mt = 0; mt < 4; mt++) {
                uint32_t a = sb + 2u * ((aRow + mt * 16) * SW_ROW + ks * 16 + aCol);
                ldsm4(A[mt], a);
            }
            #pragma unroll
            for (int np = 0; np < 2; np++) {
                uint32_t a = sb + 2u * (SW_STG + (ks * 16 + xRow) * SX_ROW + xCol + np * 16);
                ldsm4t(Bh[np], a);
            }
            #pragma unroll
            for (int mt = 0; mt < 4; mt++)
                #pragma unroll
                for (int nt = 0; nt < 4; nt++)
                    mma_f16(acc[mt][nt], A[mt], &Bh[nt >> 1][(nt & 1) * 2]);
        }
        stage = stage + 1; if (stage >= NSTG) stage -= NSTG;
    }

    unsigned short* Mb = g_M + (size_t)bxi * (O_ * NTP);
    #pragma unroll
    for (int mt = 0; mt < 4; mt++) {
        #pragma unroll
        for (int nt = 0; nt < 4; nt++) {
            int o = o0 + wo + mt * 16 + gid;
            int pix = n0 + wp + nt * 8 + tid4 * 2;
            *(uint32_t*)&Mb[(size_t)o * NTP + pix]       = h2u(acc[mt][nt][0], acc[mt][nt][1]);
            *(uint32_t*)&Mb[(size_t)(o + 8) * NTP + pix] = h2u(acc[mt][nt][2], acc[mt][nt][3]);
        }
    }
}

// ---------------- Kernel 5: inverse transform, 4-tile vector groups ----------
__global__ void __launch_bounds__(256)
inverseT_kernel(float* __restrict__ out) {
    const int o = blockIdx.x, b = blockIdx.y;
    const size_t mbase = ((size_t)(b * NXI)) * O_ * NTP + (size_t)o * NTP;
    const size_t obase = ((size_t)(b * O_ + o)) * NPIX;

    for (int g = threadIdx.x; g < NT / 4; g += 256) {
        int t0 = g * 4;
        int ty = t0 / 28, tx0 = t0 % 28;
        float m[16][4];
        #pragma unroll
        for (int xi = 0; xi < 16; xi++) {
            uint2 v = *(const uint2*)&g_M[mbase + (size_t)xi * (O_ * NTP) + t0];
            __half2 h0 = *(__half2*)&v.x;
            __half2 h1 = *(__half2*)&v.y;
            m[xi][0] = __low2float(h0);  m[xi][1] = __high2float(h0);
            m[xi][2] = __low2float(h1);  m[xi][3] = __high2float(h1);
        }
        float row0[8], row1[8];
        #pragma unroll
        for (int j = 0; j < 4; j++) {
            float sr0[4], sr1[4];
            #pragma unroll
            for (int c = 0; c < 4; c++) {
                sr0[c] = m[0 * 4 + c][j] + m[1 * 4 + c][j] + m[2 * 4 + c][j];
                sr1[c] = m[1 * 4 + c][j] - m[2 * 4 + c][j] - m[3 * 4 + c][j];
            }
            row0[j * 2 + 0] = sr0[0] + sr0[1] + sr0[2];
            row0[j * 2 + 1] = sr0[1] - sr0[2] - sr0[3];
            row1[j * 2 + 0] = sr1[0] + sr1[1] + sr1[2];
            row1[j * 2 + 1] = sr1[1] - sr1[2] - sr1[3];
        }
        size_t pb = obase + (size_t)(2 * ty) * HW_ + 2 * tx0;
        *(float4*)&out[pb]           = make_float4(row0[0], row0[1], row0[2], row0[3]);
        *(float4*)&out[pb + 4]       = make_float4(row0[4], row0[5], row0[6], row0[7]);
        *(float4*)&out[pb + HW_]     = make_float4(row1[0], row1[1], row1[2], row1[3]);
        *(float4*)&out[pb + HW_ + 4] = make_float4(row1[4], row1[5], row1[6], row1[7]);
    }
}

extern "C" void kernel_launch(void* const* d_in, const int* in_sizes, int n_in,
                              void* d_out, int out_size) {
    const float* x    = (const float*)d_in[0];
    const float* kern = (const float*)d_in[1];
    const float* w1   = (const float*)d_in[2];
    const float* b1   = (const float*)d_in[3];
    const float* w2   = (const float*)d_in[4];
    const float* b2   = (const float*)d_in[5];
    float* out = (float*)d_out;

    cudaFuncSetAttribute(wino_gemm, cudaFuncAttributeMaxDynamicSharedMemorySize, SMEM_BYTES);
    cudaFuncSetAttribute(mixU_kernel, cudaFuncAttributeMaxDynamicSharedMemorySize, MIX_SMEM);

    inputT_kernel<<<dim3(C_, B_, 2), 256>>>(x);
    mlp_kernel<<<1, 256>>>(w1, b1, w2, b2);
    mixU_kernel<<<O_, 256, MIX_SMEM>>>(kern);
    wino_gemm<<<dim3(7, 2, B_ * NXI), 256, SMEM_BYTES>>>(0);
    inverseT_kernel<<<dim3(O_, B_), 256>>>(out);
}

// round 17
// speedup vs baseline: 1.0371x; 1.0328x over previous
#include <cuda_runtime.h>
#include <cuda_bf16.h>
#include <cuda_fp16.h>
#include <cstdint>

// ---------------- dims ----------------
#define B_    16
#define C_    256
#define O_    256
#define HW_   56
#define NPIX  3136
#define NK    8
#define HID   64
#define NKEL  589824          // 256*256*9 per bank
#define NT    784             // 28*28 winograd tiles
#define NTP   896             // padded tiles (7*128)
#define NXI   16

#define NCHUNK2 4
#define NSTG   3

// GEMM smem (fp16 units)
#define SW_ROW   72
#define SX_ROW   136
#define SW_STG   (128 * SW_ROW)               // 9216
#define SX_STG   (64 * SX_ROW)                // 8704
#define STG_ELEMS (SW_STG + SX_STG)           // 17920
#define SMEM_BYTES (NSTG * STG_ELEMS * 2)     // 107520
// mixU union smem: sal(128) + ws(max(8*2304, 4096+1024+128)=18432) floats
#define MIX_SMEM  ((128 + 8 * 2304) * 4)      // 74240

__device__ float g_pooled[B_ * C_];
// V: [b*16+xi][ic][NTP] fp16
__device__ __align__(16) unsigned short g_V[(size_t)B_ * NXI * C_ * NTP];
// U: [b*16+xi][o][ic] fp16
__device__ __align__(16) unsigned short g_U[(size_t)B_ * NXI * O_ * C_];
// M: [b*16+xi][o][NTP] fp16
__device__ __align__(16) unsigned short g_M[(size_t)B_ * NXI * O_ * NTP];

// ---------------- asm helpers ----------------
__device__ __forceinline__ uint32_t smem_u32(const void* p) {
    uint32_t a;
    asm("{ .reg .u64 t; cvta.to.shared.u64 t, %1; cvt.u32.u64 %0, t; }" : "=r"(a) : "l"(p));
    return a;
}
#define CP16(dst, src) asm volatile("cp.async.cg.shared.global [%0], [%1], 16;" :: "r"(dst), "l"(src))
#define CP_COMMIT()    asm volatile("cp.async.commit_group;" ::: "memory")
#define CP_WAIT(n)     asm volatile("cp.async.wait_group %0;" :: "n"(n) : "memory")

__device__ __forceinline__ void ldsm4(uint32_t* r, uint32_t a) {
    asm volatile("ldmatrix.sync.aligned.m8n8.x4.shared.b16 {%0,%1,%2,%3}, [%4];"
                 : "=r"(r[0]), "=r"(r[1]), "=r"(r[2]), "=r"(r[3]) : "r"(a));
}
__device__ __forceinline__ void ldsm4t(uint32_t* r, uint32_t a) {
    asm volatile("ldmatrix.sync.aligned.m8n8.x4.trans.shared.b16 {%0,%1,%2,%3}, [%4];"
                 : "=r"(r[0]), "=r"(r[1]), "=r"(r[2]), "=r"(r[3]) : "r"(a));
}
__device__ __forceinline__ void mma_f16(float* d, const uint32_t* a, const uint32_t* b) {
    asm volatile("mma.sync.aligned.m16n8k16.row.col.f32.f16.f16.f32 "
                 "{%0,%1,%2,%3}, {%4,%5,%6,%7}, {%8,%9}, {%0,%1,%2,%3};"
                 : "+f"(d[0]), "+f"(d[1]), "+f"(d[2]), "+f"(d[3])
                 : "r"(a[0]), "r"(a[1]), "r"(a[2]), "r"(a[3]), "r"(b[0]), "r"(b[1]));
}
__device__ __forceinline__ uint32_t h2u(float a, float b) {
    __half2 h = __floats2half2_rn(a, b);
    return *(uint32_t*)&h;
}

// ---------------- Kernel 1: input transform V = B^T d B (+pool fused) ----------
// (R12-proven monolithic version)
__global__ void __launch_bounds__(256)
inputT_kernel(const float* __restrict__ x) {
    const int ic = blockIdx.x, b = blockIdx.y;
    __shared__ float sp[NPIX];
    __shared__ float red[8];
    const float4* xp = (const float4*)(x + ((size_t)(b * C_ + ic)) * NPIX);
    float s = 0.f;
    for (int i = threadIdx.x; i < NPIX / 4; i += 256) {
        float4 v = xp[i];
        *(float4*)&sp[i * 4] = v;
        s += (v.x + v.y) + (v.z + v.w);
    }
    #pragma unroll
    for (int o = 16; o > 0; o >>= 1) s += __shfl_xor_sync(0xffffffffu, s, o);
    if ((threadIdx.x & 31) == 0) red[threadIdx.x >> 5] = s;
    __syncthreads();
    if (threadIdx.x < 8) {
        s = red[threadIdx.x];
        #pragma unroll
        for (int o = 4; o > 0; o >>= 1) s += __shfl_xor_sync(0xffu, s, o);
        if (threadIdx.x == 0) g_pooled[b * C_ + ic] = s * (1.0f / NPIX);
    }

    const size_t vbase = ((size_t)(b * NXI)) * C_ * NTP + (size_t)ic * NTP;

    for (int p = threadIdx.x; p < NT / 2; p += 256) {
        int t0 = p * 2;
        int ty = t0 / 28, tx0 = t0 % 28;
        int r0 = 2 * ty - 1, c0 = 2 * tx0 - 1;
        float d[4][6];
        #pragma unroll
        for (int i = 0; i < 4; i++) {
            int r = r0 + i;
            bool rv = (r >= 0 && r < HW_);
            #pragma unroll
            for (int j = 0; j < 6; j++) {
                int c = c0 + j;
                d[i][j] = (rv && c >= 0 && c < HW_) ? sp[r * HW_ + c] : 0.f;
            }
        }
        float V0[16], V1[16];
        #pragma unroll
        for (int tt = 0; tt < 2; tt++) {
            int jo = 2 * tt;
            float tr[4][4];
            #pragma unroll
            for (int c = 0; c < 4; c++) {
                tr[0][c] = d[0][jo + c] - d[2][jo + c];
                tr[1][c] = d[1][jo + c] + d[2][jo + c];
                tr[2][c] = d[2][jo + c] - d[1][jo + c];
                tr[3][c] = d[1][jo + c] - d[3][jo + c];
            }
            float* V = tt ? V1 : V0;
            #pragma unroll
            for (int r = 0; r < 4; r++) {
                V[r * 4 + 0] = tr[r][0] - tr[r][2];
                V[r * 4 + 1] = tr[r][1] + tr[r][2];
                V[r * 4 + 2] = tr[r][2] - tr[r][1];
                V[r * 4 + 3] = tr[r][1] - tr[r][3];
            }
        }
        #pragma unroll
        for (int xi = 0; xi < 16; xi++) {
            size_t idx = vbase + (size_t)xi * (C_ * NTP) + t0;
            *(uint32_t*)&g_V[idx] = h2u(V0[xi], V1[xi]);
        }
    }
    for (int p = threadIdx.x; p < (NTP - NT) / 2; p += 256) {
        int t0 = NT + p * 2;
        #pragma unroll
        for (int xi = 0; xi < 16; xi++) {
            size_t idx = vbase + (size_t)xi * (C_ * NTP) + t0;
            *(uint32_t*)&g_V[idx] = 0u;
        }
    }
}

// ---------------- Kernel 2: MLP (union smem) + weight mix + transform U --------
// Phase A uses ws as sp/sh/sc for the redundant-per-block MLP; Phase B reuses
// the SAME region as sv (kernel-bank stage). Zero smem growth vs R12 mixU.
extern __shared__ float mixsm[];
__global__ void __launch_bounds__(256)
mixU_kernel(const float* __restrict__ kern,
            const float* __restrict__ w1, const float* __restrict__ b1,
            const float* __restrict__ w2, const float* __restrict__ b2) {
    float* sal = mixsm;                    // [128]
    float* ws  = mixsm + 128;              // [18432] union region
    const int o = blockIdx.x, tid = threadIdx.x;

    // ---- Phase A: MLP + softmax (redundant per block, deterministic) ----
    {
        float* sp = ws;                    // [4096]
        float* sh = ws + B_ * C_;          // [1024]
        float* sc = sh + B_ * HID;         // [128]
        for (int i = tid; i < B_ * C_; i += 256) sp[i] = g_pooled[i];
        __syncthreads();
        for (int t = tid; t < B_ * HID; t += 256) {
            int b = t >> 6, j = t & 63;
            float s = b1[j];
            #pragma unroll 8
            for (int c = 0; c < C_; c++) s = fmaf(sp[b * C_ + c], w1[c * HID + j], s);
            sh[t] = fmaxf(s, 0.f);
        }
        __syncthreads();
        if (tid < B_ * NK) {
            int b = tid >> 3, k = tid & 7;
            float s = b2[k];
            #pragma unroll
            for (int j = 0; j < HID; j++) s = fmaf(sh[b * HID + j], w2[j * NK + k], s);
            sc[tid] = s;
        }
        __syncthreads();
        if (tid < B_) {
            float m = -1e30f;
            #pragma unroll
            for (int k = 0; k < NK; k++) m = fmaxf(m, sc[tid * NK + k]);
            float e[NK], sum = 0.f;
            #pragma unroll
            for (int k = 0; k < NK; k++) { e[k] = __expf(sc[tid * NK + k] - m); sum += e[k]; }
            float inv = 1.0f / sum;
            #pragma unroll
            for (int k = 0; k < NK; k++) sal[tid * NK + k] = e[k] * inv;
        }
        __syncthreads();
    }

    // ---- Phase B: kernel-bank stage (overlays Phase A workspace) ----
    float* sv = ws;                        // [8][2304]
    #pragma unroll
    for (int k = 0; k < 8; k++)
        for (int i = tid; i < 2304; i += 256)
            sv[k * 2304 + i] = kern[(size_t)k * NKEL + (size_t)o * 2304 + i];
    __syncthreads();

    const int ic = tid;
    #pragma unroll
    for (int b = 0; b < B_; b++) {
        float g[3][3];
        #pragma unroll
        for (int r = 0; r < 3; r++)
            #pragma unroll
            for (int c = 0; c < 3; c++) {
                float sum = 0.f;
                #pragma unroll
                for (int k = 0; k < 8; k++)
                    sum = fmaf(sal[b * NK + k], sv[k * 2304 + ic * 9 + r * 3 + c], sum);
                g[r][c] = sum;
            }
        float q[4][3];
        #pragma unroll
        for (int c = 0; c < 3; c++) {
            q[0][c] = g[0][c];
            q[1][c] = 0.5f * (g[0][c] + g[1][c] + g[2][c]);
            q[2][c] = 0.5f * (g[0][c] - g[1][c] + g[2][c]);
            q[3][c] = g[2][c];
        }
        #pragma unroll
        for (int r = 0; r < 4; r++) {
            float U0 = q[r][0];
            float U1 = 0.5f * (q[r][0] + q[r][1] + q[r][2]);
            float U2 = 0.5f * (q[r][0] - q[r][1] + q[r][2]);
            float U3 = q[r][2];
            int xibase = r * 4;
            size_t base = ((size_t)(b * NXI) * O_ + o) * C_ + ic;
            g_U[base + (size_t)(xibase + 0) * (O_ * C_)] = __half_as_ushort(__float2half_rn(U0));
            g_U[base + (size_t)(xibase + 1) * (O_ * C_)] = __half_as_ushort(__float2half_rn(U1));
            g_U[base + (size_t)(xibase + 2) * (O_ * C_)] = __half_as_ushort(__float2half_rn(U2));
            g_U[base + (size_t)(xibase + 3) * (O_ * C_)] = __half_as_ushort(__float2half_rn(U3));
        }
    }
}

// ---------------- Kernel 3: batched GEMM M[bxi] = U[bxi] * V[bxi] ----------------
extern __shared__ __align__(16) unsigned short dynsm[];

__global__ void __launch_bounds__(256, 2)
wino_gemm(int dummy) {
    const int tid = threadIdx.x;
    const int n0 = blockIdx.x * 128;
    const int o0 = blockIdx.y * 128;
    const int bxi = blockIdx.z;

    const int warp = tid >> 5, L = tid & 31;
    const int wo = (warp >> 2) << 6;
    const int wp = (warp & 3) << 5;
    const int gid = L >> 2, tid4 = L & 3;

    const uint32_t sbase = smem_u32(dynsm);
    const int aRow = wo + (L & 15);
    const int aCol = (L >> 4) << 3;
    const int xRow = L & 15;
    const int xCol = wp + ((L >> 4) << 3);

    int wRow[4], wJ[4], xKK[4], xJ[4];
    #pragma unroll
    for (int i = 0; i < 4; i++) {
        int e = tid + i * 256;
        wRow[i] = e >> 3; wJ[i] = e & 7;
        xKK[i] = e >> 4; xJ[i] = e & 15;
    }

    float acc[4][4][4];
    #pragma unroll
    for (int mt = 0; mt < 4; mt++)
        #pragma unroll
        for (int nt = 0; nt < 4; nt++)
            #pragma unroll
            for (int r = 0; r < 4; r++) acc[mt][nt][r] = 0.f;

    const unsigned short* Ub = g_U + (size_t)bxi * (O_ * C_);
    const unsigned short* Vb = g_V + (size_t)bxi * (C_ * NTP);

    auto load_chunk = [&](int c, int stg) {
        uint32_t sb = sbase + (uint32_t)stg * (STG_ELEMS * 2);
        #pragma unroll
        for (int i = 0; i < 4; i++) {
            const unsigned short* srcw = Ub + (size_t)(o0 + wRow[i]) * C_ + c * 64 + wJ[i] * 8;
            CP16(sb + 2u * (wRow[i] * SW_ROW + wJ[i] * 8), srcw);
            const unsigned short* srcx = Vb + (size_t)(c * 64 + xKK[i]) * NTP + n0 + xJ[i] * 8;
            CP16(sb + 2u * (SW_STG + xKK[i] * SX_ROW + xJ[i] * 8), srcx);
        }
    };

    load_chunk(0, 0); CP_COMMIT();
    load_chunk(1, 1); CP_COMMIT();

    int stage = 0;
    for (int c = 0; c < NCHUNK2; c++) {
        if (c < NCHUNK2 - 1) { CP_WAIT(1); } else { CP_WAIT(0); }
        __syncthreads();
        if (c + 2 < NCHUNK2) {
            int s2 = stage + 2; if (s2 >= NSTG) s2 -= NSTG;
            load_chunk(c + 2, s2);
            CP_COMMIT();
        }

        const uint32_t sb = sbase + (uint32_t)stage * (STG_ELEMS * 2);
        #pragma unroll
        for (int ks = 0; ks < 4; ks++) {
            uint32_t A[4][4], Bh[2][4];
            #pragma unroll
            for (int mt = 0; mt < 4; mt++) {
                uint32_t a = sb + 2u * ((aRow + mt * 16) * SW_ROW + ks * 16 + aCol);
                ldsm4(A[mt], a);
            }
            #pragma unroll
            for (int np = 0; np < 2; np++) {
                uint32_t a = sb + 2u * (SW_STG + (ks * 16 + xRow) * SX_ROW + xCol + np * 16);
                ldsm4t(Bh[np], a);
            }
            #pragma unroll
            for (int mt = 0; mt < 4; mt++)
                #pragma unroll
                for (int nt = 0; nt < 4; nt++)
                    mma_f16(acc[mt][nt], A[mt], &Bh[nt >> 1][(nt & 1) * 2]);
        }
        stage = stage + 1; if (stage >= NSTG) stage -= NSTG;
    }

    unsigned short* Mb = g_M + (size_t)bxi * (O_ * NTP);
    #pragma unroll
    for (int mt = 0; mt < 4; mt++) {
        #pragma unroll
        for (int nt = 0; nt < 4; nt++) {
            int o = o0 + wo + mt * 16 + gid;
            int pix = n0 + wp + nt * 8 + tid4 * 2;
            *(uint32_t*)&Mb[(size_t)o * NTP + pix]       = h2u(acc[mt][nt][0], acc[mt][nt][1]);
            *(uint32_t*)&Mb[(size_t)(o + 8) * NTP + pix] = h2u(acc[mt][nt][2], acc[mt][nt][3]);
        }
    }
}

// ---------------- Kernel 4: inverse transform, 4-tile vector groups ----------
__global__ void __launch_bounds__(256)
inverseT_kernel(float* __restrict__ out) {
    const int o = blockIdx.x, b = blockIdx.y;
    const size_t mbase = ((size_t)(b * NXI)) * O_ * NTP + (size_t)o * NTP;
    const size_t obase = ((size_t)(b * O_ + o)) * NPIX;

    for (int g = threadIdx.x; g < NT / 4; g += 256) {
        int t0 = g * 4;
        int ty = t0 / 28, tx0 = t0 % 28;
        float m[16][4];
        #pragma unroll
        for (int xi = 0; xi < 16; xi++) {
            uint2 v = *(const uint2*)&g_M[mbase + (size_t)xi * (O_ * NTP) + t0];
            __half2 h0 = *(__half2*)&v.x;
            __half2 h1 = *(__half2*)&v.y;
            m[xi][0] = __low2float(h0);  m[xi][1] = __high2float(h0);
            m[xi][2] = __low2float(h1);  m[xi][3] = __high2float(h1);
        }
        float row0[8], row1[8];
        #pragma unroll
        for (int j = 0; j < 4; j++) {
            float sr0[4], sr1[4];
            #pragma unroll
            for (int c = 0; c < 4; c++) {
                sr0[c] = m[0 * 4 + c][j] + m[1 * 4 + c][j] + m[2 * 4 + c][j];
                sr1[c] = m[1 * 4 + c][j] - m[2 * 4 + c][j] - m[3 * 4 + c][j];
            }
            row0[j * 2 + 0] = sr0[0] + sr0[1] + sr0[2];
            row0[j * 2 + 1] = sr0[1] - sr0[2] - sr0[3];
            row1[j * 2 + 0] = sr1[0] + sr1[1] + sr1[2];
            row1[j * 2 + 1] = sr1[1] - sr1[2] - sr1[3];
        }
        size_t pb = obase + (size_t)(2 * ty) * HW_ + 2 * tx0;
        *(float4*)&out[pb]           = make_float4(row0[0], row0[1], row0[2], row0[3]);
        *(float4*)&out[pb + 4]       = make_float4(row0[4], row0[5], row0[6], row0[7]);
        *(float4*)&out[pb + HW_]     = make_float4(row1[0], row1[1], row1[2], row1[3]);
        *(float4*)&out[pb + HW_ + 4] = make_float4(row1[4], row1[5], row1[6], row1[7]);
    }
}

extern "C" void kernel_launch(void* const* d_in, const int* in_sizes, int n_in,
                              void* d_out, int out_size) {
    const float* x    = (const float*)d_in[0];
    const float* kern = (const float*)d_in[1];
    const float* w1   = (const float*)d_in[2];
    const float* b1   = (const float*)d_in[3];
    const float* w2   = (const float*)d_in[4];
    const float* b2   = (const float*)d_in[5];
    float* out = (float*)d_out;

    cudaFuncSetAttribute(wino_gemm, cudaFuncAttributeMaxDynamicSharedMemorySize, SMEM_BYTES);
    cudaFuncSetAttribute(mixU_kernel, cudaFuncAttributeMaxDynamicSharedMemorySize, MIX_SMEM);

    inputT_kernel<<<dim3(C_, B_), 256>>>(x);
    mixU_kernel<<<O_, 256, MIX_SMEM>>>(kern, w1, b1, w2, b2);
    wino_gemm<<<dim3(7, 2, B_ * NXI), 256, SMEM_BYTES>>>(0);
    inverseT_kernel<<<dim3(O_, B_), 256>>>(out);
}